// round 1
// baseline (speedup 1.0000x reference)
#include <cuda_runtime.h>
#include <math.h>

#define CIN  2048
#define CHID 1024
#define CEMB 256
#define BB   4
#define TT   2048

// ---------------- scratch (static device globals; no allocations) ----------
__device__ float g_XTheta[(size_t)BB*TT*CHID];  // XT[b][s][h] = sum_k theta_w[h,k] x[b,s,k] + theta_b[h]
__device__ float g_XPhi  [(size_t)BB*TT*CHID];  // XP[b][t][h]
__device__ float g_XG    [(size_t)BB*TT*CHID];  // XG[b][t][h]
__device__ float g_S1    [(size_t)BB*TT*TT];    // x x^T logits
__device__ float g_S2    [(size_t)BB*TT*TT];    // att logits
__device__ float g_Moca  [(size_t)BB*TT*TT];
__device__ float g_Y     [(size_t)BB*TT*CHID];  // Y[b][s][h] = sum_t Moca[b][t][s] XG[b][t][h]
__device__ float g_Z     [(size_t)BB*TT*CIN];   // Z[b][s][c] = sum_h Y[s,h] w_w[c,h] + w_b[c] + x[s,c]

// ---------------- generic tiled SGEMM ---------------------------------------
// TN=false: C[m,n] = sum_k A[m,k]*B[n,k]  (A: MxK row-major, B: NxK row-major)
// TN=true : C[m,n] = sum_k A[k,m]*B[k,n]  (A: KxM row-major, B: KxN row-major)
// Optional: bias over n; optional elementwise add of matrix D (MxN row-major).
template<bool TN>
__global__ __launch_bounds__(256, 2)
void gemm_kernel(const float* __restrict__ A, size_t asb,
                 const float* __restrict__ Bp, size_t bsb,
                 float* __restrict__ C, size_t csb,
                 int M, int N, int K,
                 const float* __restrict__ bias,
                 const float* __restrict__ addm, size_t addsb)
{
    const int BM = 128, BN = 128, BK = 16;
    __shared__ float As[BK][BM];
    __shared__ float Bs[BK][BN];

    const int b   = blockIdx.z;
    A  += (size_t)b * asb;
    Bp += (size_t)b * bsb;
    C  += (size_t)b * csb;

    const int m0 = blockIdx.y * BM;
    const int n0 = blockIdx.x * BN;
    const int tid = threadIdx.x;
    const int tx = tid & 15;     // 0..15
    const int ty = tid >> 4;     // 0..15

    float acc[8][8];
    #pragma unroll
    for (int i = 0; i < 8; i++)
        #pragma unroll
        for (int j = 0; j < 8; j++) acc[i][j] = 0.f;

    for (int k0 = 0; k0 < K; k0 += BK) {
        if (!TN) {
            #pragma unroll
            for (int j = 0; j < 2; j++) {
                int i  = tid + j * 256;        // 0..511 float4 slots (128x16)
                int m  = i >> 2;
                int kk = (i & 3) * 4;
                float4 v = *(const float4*)&A[(size_t)(m0 + m) * K + k0 + kk];
                As[kk + 0][m] = v.x; As[kk + 1][m] = v.y;
                As[kk + 2][m] = v.z; As[kk + 3][m] = v.w;
            }
            #pragma unroll
            for (int j = 0; j < 2; j++) {
                int i  = tid + j * 256;
                int n  = i >> 2;
                int kk = (i & 3) * 4;
                float4 v = *(const float4*)&Bp[(size_t)(n0 + n) * K + k0 + kk];
                Bs[kk + 0][n] = v.x; Bs[kk + 1][n] = v.y;
                Bs[kk + 2][n] = v.z; Bs[kk + 3][n] = v.w;
            }
        } else {
            #pragma unroll
            for (int j = 0; j < 2; j++) {
                int i  = tid + j * 256;
                int kk = i >> 5;               // 0..15
                int mm = (i & 31) * 4;         // 0..124
                *(float4*)&As[kk][mm] = *(const float4*)&A[(size_t)(k0 + kk) * M + m0 + mm];
            }
            #pragma unroll
            for (int j = 0; j < 2; j++) {
                int i  = tid + j * 256;
                int kk = i >> 5;
                int nn = (i & 31) * 4;
                *(float4*)&Bs[kk][nn] = *(const float4*)&Bp[(size_t)(k0 + kk) * N + n0 + nn];
            }
        }
        __syncthreads();

        #pragma unroll
        for (int k = 0; k < BK; k++) {
            float a[8], bb[8];
            #pragma unroll
            for (int i = 0; i < 4; i++) {
                a[i]     = As[k][ty * 4 + i];
                a[4 + i] = As[k][64 + ty * 4 + i];
                bb[i]     = Bs[k][tx * 4 + i];
                bb[4 + i] = Bs[k][64 + tx * 4 + i];
            }
            #pragma unroll
            for (int i = 0; i < 8; i++)
                #pragma unroll
                for (int j = 0; j < 8; j++)
                    acc[i][j] += a[i] * bb[j];
        }
        __syncthreads();
    }

    #pragma unroll
    for (int i = 0; i < 8; i++) {
        int m = m0 + ((i < 4) ? (ty * 4 + i) : (64 + ty * 4 + i - 4));
        #pragma unroll
        for (int j = 0; j < 8; j++) {
            int n = n0 + ((j < 4) ? (tx * 4 + j) : (64 + tx * 4 + j - 4));
            float v = acc[i][j];
            if (bias) v += bias[n];
            if (addm) v += addm[(size_t)b * addsb + (size_t)m * N + n];
            C[(size_t)m * N + n] = v;
        }
    }
}

// ---------------- row softmax-combine-softmax -------------------------------
__device__ __forceinline__ float warpMax(float v) {
    #pragma unroll
    for (int o = 16; o > 0; o >>= 1) v = fmaxf(v, __shfl_xor_sync(0xffffffffu, v, o));
    return v;
}
__device__ __forceinline__ float warpSum(float v) {
    #pragma unroll
    for (int o = 16; o > 0; o >>= 1) v += __shfl_xor_sync(0xffffffffu, v, o);
    return v;
}
__device__ __forceinline__ float blockMax(float v, float* sm) {
    v = warpMax(v);
    if ((threadIdx.x & 31) == 0) sm[threadIdx.x >> 5] = v;
    __syncthreads();
    float r = sm[0];
    #pragma unroll
    for (int i = 1; i < 8; i++) r = fmaxf(r, sm[i]);
    __syncthreads();
    return r;
}
__device__ __forceinline__ float blockSum(float v, float* sm) {
    v = warpSum(v);
    if ((threadIdx.x & 31) == 0) sm[threadIdx.x >> 5] = v;
    __syncthreads();
    float r = 0.f;
    #pragma unroll
    for (int i = 0; i < 8; i++) r += sm[i];
    __syncthreads();
    return r;
}

// moca[b] = softmax(r0*P[2b] + r1*P[2b+1] + rb), P[k] = rowsoftmax(S1[k]) for k<4,
// rowsoftmax(S2[k-4]) for k>=4.  (The torch cat/view batch-interleave quirk.)
__global__ void combine_softmax(const float* __restrict__ rw, const float* __restrict__ rbp)
{
    __shared__ float sm[8];
    const int t = blockIdx.x;
    const int b = blockIdx.y;
    const float* sa;
    const float* sb;
    if (b < 2) {
        sa = g_S1 + ((size_t)(2 * b)     * TT + t) * TT;
        sb = g_S1 + ((size_t)(2 * b + 1) * TT + t) * TT;
    } else {
        sa = g_S2 + ((size_t)(2 * b - 4) * TT + t) * TT;
        sb = g_S2 + ((size_t)(2 * b - 3) * TT + t) * TT;
    }
    const float r0 = rw[0], r1 = rw[1], rc = rbp[0];
    const int tid = threadIdx.x;

    float v1[8], v2[8];
    #pragma unroll
    for (int i = 0; i < 8; i++) { v1[i] = sa[tid + i * 256]; v2[i] = sb[tid + i * 256]; }

    float m1 = -1e30f, m2 = -1e30f;
    #pragma unroll
    for (int i = 0; i < 8; i++) { m1 = fmaxf(m1, v1[i]); m2 = fmaxf(m2, v2[i]); }
    m1 = blockMax(m1, sm);
    m2 = blockMax(m2, sm);

    float s1 = 0.f, s2 = 0.f;
    #pragma unroll
    for (int i = 0; i < 8; i++) {
        v1[i] = expf(v1[i] - m1); s1 += v1[i];
        v2[i] = expf(v2[i] - m2); s2 += v2[i];
    }
    s1 = blockSum(s1, sm);
    s2 = blockSum(s2, sm);
    const float i1 = 1.f / s1, i2 = 1.f / s2;

    float mm = -1e30f;
    #pragma unroll
    for (int i = 0; i < 8; i++) {
        v1[i] = r0 * v1[i] * i1 + r1 * v2[i] * i2 + rc;
        mm = fmaxf(mm, v1[i]);
    }
    mm = blockMax(mm, sm);

    float s3 = 0.f;
    #pragma unroll
    for (int i = 0; i < 8; i++) { v1[i] = expf(v1[i] - mm); s3 += v1[i]; }
    s3 = blockSum(s3, sm);
    const float i3 = 1.f / s3;

    float* o = g_Moca + ((size_t)b * TT + t) * TT;
    #pragma unroll
    for (int i = 0; i < 8; i++) o[tid + i * 256] = v1[i] * i3;
}

// ---------------- launch -----------------------------------------------------
extern "C" void kernel_launch(void* const* d_in, const int* in_sizes, int n_in,
                              void* d_out, int out_size)
{
    const float* x       = (const float*)d_in[0];
    const float* theta_w = (const float*)d_in[1];
    const float* theta_b = (const float*)d_in[2];
    const float* phi_w   = (const float*)d_in[3];
    const float* phi_b   = (const float*)d_in[4];
    const float* g_w     = (const float*)d_in[5];
    const float* g_b     = (const float*)d_in[6];
    const float* rou_w   = (const float*)d_in[7];
    const float* rou_b   = (const float*)d_in[8];
    const float* w_w     = (const float*)d_in[9];
    const float* w_b     = (const float*)d_in[10];
    const float* emb_w   = (const float*)d_in[11];
    const float* emb_b   = (const float*)d_in[12];
    float* out = (float*)d_out;

    float *XT, *XP, *XG, *S1, *S2, *Mo, *Y, *Z;
    cudaGetSymbolAddress((void**)&XT, g_XTheta);
    cudaGetSymbolAddress((void**)&XP, g_XPhi);
    cudaGetSymbolAddress((void**)&XG, g_XG);
    cudaGetSymbolAddress((void**)&S1, g_S1);
    cudaGetSymbolAddress((void**)&S2, g_S2);
    cudaGetSymbolAddress((void**)&Mo, g_Moca);
    cudaGetSymbolAddress((void**)&Y,  g_Y);
    cudaGetSymbolAddress((void**)&Z,  g_Z);

    const size_t sX  = (size_t)TT * CIN;
    const size_t sH  = (size_t)TT * CHID;
    const size_t sTT = (size_t)TT * TT;
    const size_t sO  = (size_t)TT * CEMB;

    dim3 gProj(CHID / 128, TT / 128, BB);  // 8 x 16 x 4
    dim3 gTT  (TT   / 128, TT / 128, BB);  // 16 x 16 x 4
    dim3 gZ   (CIN  / 128, TT / 128, BB);  // 16 x 16 x 4
    dim3 gOut (CEMB / 128, TT / 128, BB);  // 2 x 16 x 4

    // Projections: (T,H) = x (T,K) . W (H,K)^T  + bias[h]
    gemm_kernel<false><<<gProj, 256>>>(x, sX, theta_w, 0, XT, sH, TT, CHID, CIN, theta_b, nullptr, 0);
    gemm_kernel<false><<<gProj, 256>>>(x, sX, phi_w,   0, XP, sH, TT, CHID, CIN, phi_b,   nullptr, 0);
    gemm_kernel<false><<<gProj, 256>>>(x, sX, g_w,     0, XG, sH, TT, CHID, CIN, g_b,     nullptr, 0);

    // S1[t,s] = x[t,:].x[s,:] ;  S2[t,s] = XP[t,:].XT[s,:]
    gemm_kernel<false><<<gTT, 256>>>(x,  sX, x,  sX, S1, sTT, TT, TT, CIN,  nullptr, nullptr, 0);
    gemm_kernel<false><<<gTT, 256>>>(XP, sH, XT, sH, S2, sTT, TT, TT, CHID, nullptr, nullptr, 0);

    // moca (with the cat/view batch-interleave)
    combine_softmax<<<dim3(TT, BB), 256>>>(rou_w, rou_b);

    // Y[s,h] = sum_t Moca[t,s] * XG[t,h]   (TN gemm)
    gemm_kernel<true><<<gProj, 256>>>(Mo, sTT, XG, sH, Y, sH, TT, CHID, TT, nullptr, nullptr, 0);

    // Z[s,c] = sum_h Y[s,h] w_w[c,h] + w_b[c] + x[s,c]
    gemm_kernel<false><<<gZ, 256>>>(Y, sH, w_w, 0, Z, sX, TT, CIN, CHID, w_b, x, sX);

    // out[t,e] = sum_c Z[t,c] emb_w[e,c] + emb_b[e]
    gemm_kernel<false><<<gOut, 256>>>(Z, sX, emb_w, 0, out, sO, TT, CEMB, CIN, emb_b, nullptr, 0);
}

// round 3
// speedup vs baseline: 2.0755x; 2.0755x over previous
#include <cuda_runtime.h>
#include <cuda_bf16.h>
#include <stdint.h>
#include <math.h>

#define CIN  2048
#define CHID 1024
#define CEMB 256
#define BB   4
#define TT   2048

// ---------------- scratch (static device globals; no allocations) ----------
__device__ float g_XT [(size_t)BB*TT*CHID];   // XT[b][t][h]
__device__ float g_XP [(size_t)BB*TT*CHID];   // XP[b][t][h]
__device__ float g_XGT[(size_t)BB*CHID*TT];   // XGT[b][h][t]
__device__ float g_S1 [(size_t)BB*TT*TT];
__device__ float g_S2 [(size_t)BB*TT*TT];
__device__ float g_Mo [(size_t)BB*TT*TT];
__device__ float g_MoT[(size_t)BB*TT*TT];
__device__ float g_Y  [(size_t)BB*TT*CHID];
__device__ float g_Z  [(size_t)BB*TT*CIN];

// ---------------- helpers ----------------------------------------------------
__device__ __forceinline__ uint32_t smem_u32(const void* p) {
    uint32_t a;
    asm("{ .reg .u64 t; cvta.to.shared.u64 t, %1; cvt.u32.u64 %0, t; }" : "=r"(a) : "l"(p));
    return a;
}
__device__ __forceinline__ void ldsm4(uint32_t* r, uint32_t addr) {
    asm volatile("ldmatrix.sync.aligned.m8n8.x4.shared.b16 {%0,%1,%2,%3}, [%4];"
        : "=r"(r[0]), "=r"(r[1]), "=r"(r[2]), "=r"(r[3]) : "r"(addr));
}
__device__ __forceinline__ void mma16816(float* c, const uint32_t* a, uint32_t b0, uint32_t b1) {
    asm volatile("mma.sync.aligned.m16n8k16.row.col.f32.bf16.bf16.f32 "
        "{%0,%1,%2,%3}, {%4,%5,%6,%7}, {%8,%9}, {%0,%1,%2,%3};"
        : "+f"(c[0]), "+f"(c[1]), "+f"(c[2]), "+f"(c[3])
        : "r"(a[0]), "r"(a[1]), "r"(a[2]), "r"(a[3]), "r"(b0), "r"(b1));
}
// fp32 -> (hi,lo) bf16 split, stored to two smem locations (4 bf16 each)
__device__ __forceinline__ void cvt_store(float4 v, uint32_t hiAddr, uint32_t loAddr) {
    uint32_t h0, h1, l0, l1;
    asm("cvt.rn.bf16x2.f32 %0, %1, %2;" : "=r"(h0) : "f"(v.y), "f"(v.x));
    asm("cvt.rn.bf16x2.f32 %0, %1, %2;" : "=r"(h1) : "f"(v.w), "f"(v.z));
    float hx = __uint_as_float(h0 << 16), hy = __uint_as_float(h0 & 0xffff0000u);
    float hz = __uint_as_float(h1 << 16), hw = __uint_as_float(h1 & 0xffff0000u);
    asm("cvt.rn.bf16x2.f32 %0, %1, %2;" : "=r"(l0) : "f"(v.y - hy), "f"(v.x - hx));
    asm("cvt.rn.bf16x2.f32 %0, %1, %2;" : "=r"(l1) : "f"(v.w - hw), "f"(v.z - hz));
    asm volatile("st.shared.v2.b32 [%0], {%1,%2};" :: "r"(hiAddr), "r"(h0), "r"(h1) : "memory");
    asm volatile("st.shared.v2.b32 [%0], {%1,%2};" :: "r"(loAddr), "r"(l0), "r"(l1) : "memory");
}

// ---------------- bf16x3 mma.sync NT GEMM -----------------------------------
// C[m,n] = sum_k A[m,k]*B[n,k]  (A: MxK, B: NxK row-major fp32)
// CTA tile 128x128, BK=32, 8 warps, warp tile 32(M)x64(N).
#define STRIDE_E   40                      // bf16 elems per smem row (80B -> conflict-free ldmatrix)
#define TILE_BYTES 10240                   // 128 rows * 40 * 2B
#define STAGE_BYTES (4*TILE_BYTES)         // A_hi, A_lo, B_hi, B_lo
#define SMEM_TOTAL  (2*STAGE_BYTES)        // 81920 B

__global__ void __launch_bounds__(256, 1)
gemm_mma(const float* __restrict__ A, size_t asb,
         const float* __restrict__ B, size_t bsb,
         float* __restrict__ C, size_t csb,
         int N, int K,
         const float* __restrict__ bias_n,
         const float* __restrict__ bias_m,
         const float* __restrict__ addm, size_t addsb)
{
    extern __shared__ char smem[];
    const uint32_t sb = smem_u32(smem);
    const int tid = threadIdx.x, lane = tid & 31, wid = tid >> 5;
    const int bz = blockIdx.z;
    A += (size_t)bz * asb;
    B += (size_t)bz * bsb;
    C += (size_t)bz * csb;
    const int m0 = blockIdx.y * 128, n0 = blockIdx.x * 128;
    const int warpM = wid & 3, warpN = wid >> 2;

    float4 ra[4], rb[4];
    auto loadRegs = [&](int it) {
        const int k0 = it * 32;
        #pragma unroll
        for (int p = 0; p < 4; p++) {
            const int idx = tid + p * 256;
            const int row = idx >> 3, c4 = idx & 7;
            ra[p] = *(const float4*)(A + (size_t)(m0 + row) * K + k0 + c4 * 4);
            rb[p] = *(const float4*)(B + (size_t)(n0 + row) * K + k0 + c4 * 4);
        }
    };
    auto storeRegs = [&](int buf) {
        const uint32_t base = sb + buf * STAGE_BYTES;
        #pragma unroll
        for (int p = 0; p < 4; p++) {
            const int idx = tid + p * 256;
            const int row = idx >> 3, c4 = idx & 7;
            const uint32_t off = (uint32_t)(row * STRIDE_E + c4 * 4) * 2;
            cvt_store(ra[p], base + off, base + TILE_BYTES + off);
            cvt_store(rb[p], base + 2 * TILE_BYTES + off, base + 3 * TILE_BYTES + off);
        }
    };

    float acc[2][8][4] = {};
    // ldmatrix per-lane base offsets (bytes): row = lane&15, k-col = (lane>>4)*8
    const uint32_t aOffB = (uint32_t)((warpM * 32 + (lane & 15)) * STRIDE_E + (lane >> 4) * 8) * 2;
    const uint32_t bOffB = (uint32_t)((warpN * 64 + (lane & 15)) * STRIDE_E + (lane >> 4) * 8) * 2;

    const int nIter = K >> 5;
    loadRegs(0);
    storeRegs(0);
    __syncthreads();

    for (int it = 0; it < nIter; ++it) {
        const int buf = it & 1;
        if (it + 1 < nIter) loadRegs(it + 1);
        const uint32_t base = sb + buf * STAGE_BYTES;
        #pragma unroll
        for (int ks = 0; ks < 2; ks++) {
            uint32_t ah[2][4], al[2][4], bh[4][4], bl[4][4];
            #pragma unroll
            for (int mf = 0; mf < 2; mf++) {
                ldsm4(ah[mf], base + aOffB + mf * 1280 + ks * 32);                 // 16 rows*80B=1280
                ldsm4(al[mf], base + TILE_BYTES + aOffB + mf * 1280 + ks * 32);
            }
            #pragma unroll
            for (int np = 0; np < 4; np++) {
                ldsm4(bh[np], base + 2 * TILE_BYTES + bOffB + np * 1280 + ks * 32);
                ldsm4(bl[np], base + 3 * TILE_BYTES + bOffB + np * 1280 + ks * 32);
            }
            #pragma unroll
            for (int mf = 0; mf < 2; mf++)
                #pragma unroll
                for (int nf = 0; nf < 8; nf++) {
                    const int np = nf >> 1, o = nf & 1;
                    mma16816(acc[mf][nf], ah[mf], bh[np][o], bh[np][2 + o]);
                    mma16816(acc[mf][nf], ah[mf], bl[np][o], bl[np][2 + o]);
                    mma16816(acc[mf][nf], al[mf], bh[np][o], bh[np][2 + o]);
                }
        }
        if (it + 1 < nIter) storeRegs((it + 1) & 1);
        __syncthreads();
    }

    // epilogue: mma fragment layout -> float2 stores
    const int r = lane >> 2, cq = (lane & 3) * 2;
    #pragma unroll
    for (int mf = 0; mf < 2; mf++) {
        #pragma unroll
        for (int half = 0; half < 2; half++) {
            const int m = m0 + warpM * 32 + mf * 16 + r + half * 8;
            const float bm = bias_m ? bias_m[m] : 0.f;
            #pragma unroll
            for (int nf = 0; nf < 8; nf++) {
                const int gn = n0 + warpN * 64 + nf * 8 + cq;
                float vx = acc[mf][nf][half * 2 + 0] + bm;
                float vy = acc[mf][nf][half * 2 + 1] + bm;
                if (bias_n) { vx += bias_n[gn]; vy += bias_n[gn + 1]; }
                if (addm) {
                    const float2 av = *(const float2*)(addm + (size_t)bz * addsb + (size_t)m * N + gn);
                    vx += av.x; vy += av.y;
                }
                *(float2*)(C + (size_t)m * N + gn) = make_float2(vx, vy);
            }
        }
    }
}

// ---------------- softmax combine -------------------------------------------
__device__ __forceinline__ float warpMax(float v) {
    #pragma unroll
    for (int o = 16; o > 0; o >>= 1) v = fmaxf(v, __shfl_xor_sync(0xffffffffu, v, o));
    return v;
}
__device__ __forceinline__ float warpSum(float v) {
    #pragma unroll
    for (int o = 16; o > 0; o >>= 1) v += __shfl_xor_sync(0xffffffffu, v, o);
    return v;
}
__device__ __forceinline__ float blockMax(float v, float* sm) {
    v = warpMax(v);
    if ((threadIdx.x & 31) == 0) sm[threadIdx.x >> 5] = v;
    __syncthreads();
    float r = sm[0];
    #pragma unroll
    for (int i = 1; i < 8; i++) r = fmaxf(r, sm[i]);
    __syncthreads();
    return r;
}
__device__ __forceinline__ float blockSum(float v, float* sm) {
    v = warpSum(v);
    if ((threadIdx.x & 31) == 0) sm[threadIdx.x >> 5] = v;
    __syncthreads();
    float r = 0.f;
    #pragma unroll
    for (int i = 0; i < 8; i++) r += sm[i];
    __syncthreads();
    return r;
}

__global__ void combine_softmax(const float* __restrict__ rw, const float* __restrict__ rbp)
{
    __shared__ float sm[8];
    const int t = blockIdx.x;
    const int b = blockIdx.y;
    const float* sa;
    const float* sbp;
    if (b < 2) {
        sa  = g_S1 + ((size_t)(2 * b)     * TT + t) * TT;
        sbp = g_S1 + ((size_t)(2 * b + 1) * TT + t) * TT;
    } else {
        sa  = g_S2 + ((size_t)(2 * b - 4) * TT + t) * TT;
        sbp = g_S2 + ((size_t)(2 * b - 3) * TT + t) * TT;
    }
    const float r0 = rw[0], r1 = rw[1], rc = rbp[0];
    const int tid = threadIdx.x;

    float v1[8], v2[8];
    #pragma unroll
    for (int i = 0; i < 8; i++) { v1[i] = sa[tid + i * 256]; v2[i] = sbp[tid + i * 256]; }

    float m1 = -1e30f, m2 = -1e30f;
    #pragma unroll
    for (int i = 0; i < 8; i++) { m1 = fmaxf(m1, v1[i]); m2 = fmaxf(m2, v2[i]); }
    m1 = blockMax(m1, sm);
    m2 = blockMax(m2, sm);

    float s1 = 0.f, s2 = 0.f;
    #pragma unroll
    for (int i = 0; i < 8; i++) {
        v1[i] = expf(v1[i] - m1); s1 += v1[i];
        v2[i] = expf(v2[i] - m2); s2 += v2[i];
    }
    s1 = blockSum(s1, sm);
    s2 = blockSum(s2, sm);
    const float i1 = 1.f / s1, i2 = 1.f / s2;

    float mm = -1e30f;
    #pragma unroll
    for (int i = 0; i < 8; i++) {
        v1[i] = r0 * v1[i] * i1 + r1 * v2[i] * i2 + rc;
        mm = fmaxf(mm, v1[i]);
    }
    mm = blockMax(mm, sm);

    float s3 = 0.f;
    #pragma unroll
    for (int i = 0; i < 8; i++) { v1[i] = expf(v1[i] - mm); s3 += v1[i]; }
    s3 = blockSum(s3, sm);
    const float i3 = 1.f / s3;

    float* o = g_Mo + ((size_t)b * TT + t) * TT;
    #pragma unroll
    for (int i = 0; i < 8; i++) o[tid + i * 256] = v1[i] * i3;
}

// ---------------- 32x32 transpose (Mo -> MoT) --------------------------------
__global__ void transpose_k(const float* __restrict__ in, float* __restrict__ out)
{
    __shared__ float t[32][33];
    const size_t bo = (size_t)blockIdx.z * TT * TT;
    const int x0 = blockIdx.x * 32, y0 = blockIdx.y * 32;
    const int tx = threadIdx.x, ty = threadIdx.y;
    #pragma unroll
    for (int i = 0; i < 32; i += 8)
        t[ty + i][tx] = in[bo + (size_t)(y0 + ty + i) * TT + x0 + tx];
    __syncthreads();
    #pragma unroll
    for (int i = 0; i < 32; i += 8)
        out[bo + (size_t)(x0 + ty + i) * TT + y0 + tx] = t[tx][ty + i];
}

// ---------------- launch -----------------------------------------------------
extern "C" void kernel_launch(void* const* d_in, const int* in_sizes, int n_in,
                              void* d_out, int out_size)
{
    const float* x       = (const float*)d_in[0];
    const float* theta_w = (const float*)d_in[1];
    const float* theta_b = (const float*)d_in[2];
    const float* phi_w   = (const float*)d_in[3];
    const float* phi_b   = (const float*)d_in[4];
    const float* g_w     = (const float*)d_in[5];
    const float* g_b     = (const float*)d_in[6];
    const float* rou_w   = (const float*)d_in[7];
    const float* rou_b   = (const float*)d_in[8];
    const float* w_w     = (const float*)d_in[9];
    const float* w_b     = (const float*)d_in[10];
    const float* emb_w   = (const float*)d_in[11];
    const float* emb_b   = (const float*)d_in[12];
    float* out = (float*)d_out;

    cudaFuncSetAttribute(gemm_mma, cudaFuncAttributeMaxDynamicSharedMemorySize, SMEM_TOTAL);

    float *XT, *XP, *XGT, *S1, *S2, *Mo, *MoT, *Y, *Z;
    cudaGetSymbolAddress((void**)&XT,  g_XT);
    cudaGetSymbolAddress((void**)&XP,  g_XP);
    cudaGetSymbolAddress((void**)&XGT, g_XGT);
    cudaGetSymbolAddress((void**)&S1,  g_S1);
    cudaGetSymbolAddress((void**)&S2,  g_S2);
    cudaGetSymbolAddress((void**)&Mo,  g_Mo);
    cudaGetSymbolAddress((void**)&MoT, g_MoT);
    cudaGetSymbolAddress((void**)&Y,   g_Y);
    cudaGetSymbolAddress((void**)&Z,   g_Z);

    const size_t sX  = (size_t)TT * CIN;
    const size_t sH  = (size_t)TT * CHID;
    const size_t sTT = (size_t)TT * TT;
    const size_t sO  = (size_t)TT * CEMB;

    // XT = x . theta_w^T + theta_b           (M=T, N=CHID, K=CIN)
    gemm_mma<<<dim3(CHID/128, TT/128, BB), 256, SMEM_TOTAL>>>(
        x, sX, theta_w, 0, XT, sH, CHID, CIN, theta_b, nullptr, nullptr, 0);
    // XP = x . phi_w^T + phi_b
    gemm_mma<<<dim3(CHID/128, TT/128, BB), 256, SMEM_TOTAL>>>(
        x, sX, phi_w, 0, XP, sH, CHID, CIN, phi_b, nullptr, nullptr, 0);
    // XGT[h][t] = g_w . x^T + g_b[h]         (M=CHID, N=T, K=CIN, bias over m)
    gemm_mma<<<dim3(TT/128, CHID/128, BB), 256, SMEM_TOTAL>>>(
        g_w, 0, x, sX, XGT, sH, TT, CIN, nullptr, g_b, nullptr, 0);
    // S1 = x . x^T                           (M=N=T, K=CIN)
    gemm_mma<<<dim3(TT/128, TT/128, BB), 256, SMEM_TOTAL>>>(
        x, sX, x, sX, S1, sTT, TT, CIN, nullptr, nullptr, nullptr, 0);
    // S2 = XP . XT^T                         (M=N=T, K=CHID)
    gemm_mma<<<dim3(TT/128, TT/128, BB), 256, SMEM_TOTAL>>>(
        XP, sH, XT, sH, S2, sTT, TT, CHID, nullptr, nullptr, nullptr, 0);
    // moca (cat/view batch-interleave) -> Mo
    combine_softmax<<<dim3(TT, BB), 256>>>(rou_w, rou_b);
    // MoT = Mo^T per batch
    transpose_k<<<dim3(TT/32, TT/32, BB), dim3(32, 8)>>>(Mo, MoT);
    // Y[s][h] = MoT . XGT^T                  (M=T, N=CHID, K=T)
    gemm_mma<<<dim3(CHID/128, TT/128, BB), 256, SMEM_TOTAL>>>(
        MoT, sTT, XGT, sH, Y, sH, CHID, TT, nullptr, nullptr, nullptr, 0);
    // Z = Y . w_w^T + w_b + x                (M=T, N=CIN, K=CHID)
    gemm_mma<<<dim3(CIN/128, TT/128, BB), 256, SMEM_TOTAL>>>(
        Y, sH, w_w, 0, Z, sX, CIN, CHID, w_b, nullptr, x, sX);
    // out = Z . emb_w^T + emb_b              (M=T, N=CEMB, K=CIN)
    gemm_mma<<<dim3(CEMB/128, TT/128, BB), 256, SMEM_TOTAL>>>(
        Z, sX, emb_w, 0, out, sO, CEMB, CIN, emb_b, nullptr, nullptr, 0);
}